// round 3
// baseline (speedup 1.0000x reference)
#include <cuda_runtime.h>

// ---------------- geometry ----------------
#define TX 32
#define TY 8
#define HXP 36                 // TX + 4 (x halo)
#define ZCHUNK 64
#define NBLOCKS 1024           // 4 * 16 * 16
#define YB  (TY*HXP)           // 288 floats per channel plane
#define BUF (5*YB)             // 1440 floats per ych buffer

// 1-D separable Gaussian (sigma=1.5, window=5), normalized; literals -> FFMA-imm.
#define G0 0.12007838f
#define G1 0.23388076f
#define G2 0.29208171f

#define C1f 1.0e-4f            // 0.01^2
#define C2f 9.0e-4f            // 0.03^2

__device__ float g_partials[NBLOCKS];

__global__ void __launch_bounds__(256, 4)
ssim_main(const float* __restrict__ X, const float* __restrict__ Y)
{
    __shared__ float ych[2 * BUF];     // double-buffered 5-channel y-convolved planes

    const int tid = threadIdx.x;
    const int nc  = blockIdx.z >> 1;                 // 0..7 (n*4 + c)
    const int zb  = (blockIdx.z & 1) * ZCHUNK;       // 0 or 64
    const int y0  = blockIdx.y * TY;
    const int x0  = blockIdx.x * TX;
    const float* Xb = X + (size_t)nc * (128 * 128 * 128);
    const float* Yb = Y + (size_t)nc * (128 * 128 * 128);

    // ---------- loop-invariant task geometry ----------
    // task 1: j = tid  ->  yy = j/36, w = j%36   (computed ONCE)
    const int yy1 = tid / HXP;
    const int w1  = tid - yy1 * HXP;
    const int gh1 = y0 + yy1 - 2;
    const int gw1 = x0 + w1 - 2;
    unsigned rm1 = 0;
    #pragma unroll
    for (int t = 0; t < 5; t++)
        if ((unsigned)(gh1 + t) < 128u && (unsigned)gw1 < 128u) rm1 |= 1u << t;
    const float* px1 = Xb + ((zb - 2) * 16384 + gh1 * 128 + gw1);
    const float* py1 = Yb + ((zb - 2) * 16384 + gh1 * 128 + gw1);

    // task 2 (warp 0 only): j = 256+tid -> yy = 7, w = tid+4
    const bool has2 = (tid < 32);
    const int gh2 = y0 + 5;            // 7 - 2
    const int gw2 = x0 + tid + 2;      // (tid+4) - 2
    unsigned rm2 = 0;
    #pragma unroll
    for (int t = 0; t < 5; t++)
        if ((unsigned)(gh2 + t) < 128u && (unsigned)gw2 < 128u) rm2 |= 1u << t;
    const float* px2 = Xb + ((zb - 2) * 16384 + gh2 * 128 + gw2);
    const float* py2 = Yb + ((zb - 2) * 16384 + gh2 * 128 + gw2);

    // phase-2 output column (one warp per y row)
    const int ox = tid & 31;
    const int oy = tid >> 5;
    const int xb = oy * HXP + ox;

    // z-conv ring accumulators: 5 channels x 5 in-flight output planes
    float a0[5], a1[5], a2[5], a3[5], a4[5];
    #pragma unroll
    for (int i = 0; i < 5; i++) { a0[i] = a1[i] = a2[i] = a3[i] = a4[i] = 0.f; }

    float lsum = 0.f;
    const float GW[5] = {G0, G1, G2, G1, G0};

    int pb = 0;            // ych buffer offset (0 or BUF)
    int zp = zb - 2;

    for (int grp = 0; grp < 14; ++grp) {
        #pragma unroll
        for (int s = 0; s < 5; ++s) {
            const int it = grp * 5 + s;
            const bool zok = (unsigned)zp < 128u;

            // ---- phase 1: fused load + channel formation + y-conv ----
            {
                float s0 = 0.f, s1 = 0.f, s2 = 0.f, s3 = 0.f, s4 = 0.f;
                #pragma unroll
                for (int t = 0; t < 5; t++) {
                    const bool m = zok && ((rm1 >> t) & 1);
                    float vx = m ? px1[t * 128] : 0.f;
                    float vy = m ? py1[t * 128] : 0.f;
                    float a = m ? fmaf(vx, 0.5f, 0.5f) : 0.f;
                    float b = m ? fmaf(vy, 0.5f, 0.5f) : 0.f;
                    float g = GW[t];
                    float ga = g * a, gb = g * b;
                    s0 += ga;
                    s1 += gb;
                    s2 = fmaf(ga, a, s2);
                    s3 = fmaf(gb, b, s3);
                    s4 = fmaf(ga, b, s4);
                }
                float* wr = ych + pb + tid;
                wr[0]      = s0;
                wr[YB]     = s1;
                wr[2 * YB] = s2;
                wr[3 * YB] = s3;
                wr[4 * YB] = s4;
            }
            if (has2) {
                float s0 = 0.f, s1 = 0.f, s2 = 0.f, s3 = 0.f, s4 = 0.f;
                #pragma unroll
                for (int t = 0; t < 5; t++) {
                    const bool m = zok && ((rm2 >> t) & 1);
                    float vx = m ? px2[t * 128] : 0.f;
                    float vy = m ? py2[t * 128] : 0.f;
                    float a = m ? fmaf(vx, 0.5f, 0.5f) : 0.f;
                    float b = m ? fmaf(vy, 0.5f, 0.5f) : 0.f;
                    float g = GW[t];
                    float ga = g * a, gb = g * b;
                    s0 += ga;
                    s1 += gb;
                    s2 = fmaf(ga, a, s2);
                    s3 = fmaf(gb, b, s3);
                    s4 = fmaf(ga, b, s4);
                }
                float* wr = ych + pb + 256 + tid;
                wr[0]      = s0;
                wr[YB]     = s1;
                wr[2 * YB] = s2;
                wr[3 * YB] = s3;
                wr[4 * YB] = s4;
            }
            __syncthreads();    // the ONLY barrier per plane (double buffer covers WAR)

            // ---- phase 2: x-conv ----
            const float* rd = ych + pb + xb;
            #define XC(c) (G2 * rd[(c)*YB + 2] \
                         + G1 * (rd[(c)*YB + 1] + rd[(c)*YB + 3]) \
                         + G0 * (rd[(c)*YB] + rd[(c)*YB + 4]))
            float v0 = XC(0), v1 = XC(1), v2 = XC(2), v3 = XC(3), v4 = XC(4);
            #undef XC

            // ---- z accumulation (slot index static after unroll) ----
            #pragma unroll
            for (int k = 0; k < 5; ++k) {
                const int sl = (s + k) % 5;
                float g = GW[k];
                a0[sl] = fmaf(g, v0, a0[sl]);
                a1[sl] = fmaf(g, v1, a1[sl]);
                a2[sl] = fmaf(g, v2, a2[sl]);
                a3[sl] = fmaf(g, v3, a3[sl]);
                a4[sl] = fmaf(g, v4, a4[sl]);
            }

            // ---- slot s complete -> SSIM for output plane zb + it - 4 ----
            if ((unsigned)(it - 4) < 64u) {
                float mu1 = a0[s], mu2 = a1[s];
                float mu1s = mu1 * mu1, mu2s = mu2 * mu2, mu12 = mu1 * mu2;
                float sg1  = a2[s] - mu1s;
                float sg2  = a3[s] - mu2s;
                float sg12 = a4[s] - mu12;
                float num = (2.f * mu12 + C1f) * (2.f * sg12 + C2f);
                float den = (mu1s + mu2s + C1f) * (sg1 + sg2 + C2f);
                lsum += __fdividef(num, den);
            }
            a0[s] = 0.f; a1[s] = 0.f; a2[s] = 0.f; a3[s] = 0.f; a4[s] = 0.f;

            pb ^= BUF;
            zp++;
            px1 += 16384; py1 += 16384;
            px2 += 16384; py2 += 16384;
        }
    }

    // ---- block reduction ----
    #pragma unroll
    for (int o = 16; o; o >>= 1)
        lsum += __shfl_xor_sync(0xffffffffu, lsum, o);
    __syncthreads();
    if ((tid & 31) == 0) ych[tid >> 5] = lsum;
    __syncthreads();
    if (tid == 0) {
        float t = 0.f;
        #pragma unroll
        for (int i = 0; i < 8; i++) t += ych[i];
        g_partials[(blockIdx.z * 16 + blockIdx.y) * 4 + blockIdx.x] = t;
    }
}

__global__ void ssim_reduce(float* __restrict__ out)
{
    __shared__ double sd[256];
    double s = 0.0;
    for (int i = threadIdx.x; i < NBLOCKS; i += 256)
        s += (double)g_partials[i];
    sd[threadIdx.x] = s;
    __syncthreads();
    #pragma unroll
    for (int st = 128; st; st >>= 1) {
        if (threadIdx.x < st) sd[threadIdx.x] += sd[threadIdx.x + st];
        __syncthreads();
    }
    if (threadIdx.x == 0)
        out[0] = (float)(sd[0] * (1.0 / 16777216.0));
}

extern "C" void kernel_launch(void* const* d_in, const int* in_sizes, int n_in,
                              void* d_out, int out_size)
{
    const float* X = (const float*)d_in[0];
    const float* Y = (const float*)d_in[1];
    // d_in[2] is the Gaussian kernel; weights are baked in as literals.

    dim3 grid(4, 16, 16);    // x-tiles, y-tiles, nc*2 z-chunks
    ssim_main<<<grid, 256>>>(X, Y);
    ssim_reduce<<<1, 256>>>((float*)d_out);
}

// round 4
// speedup vs baseline: 1.3339x; 1.3339x over previous
#include <cuda_runtime.h>

// ---------------- geometry ----------------
#define TX 32
#define TY 8
#define HXP 36                 // TX + 4
#define NTHREADS 288           // = TY * HXP / 1  -> exactly one phase-1 task per thread
#define ZCHUNK 64
#define NBLOCKS 1024           // 4 * 16 * 16
#define YB  (TY*HXP)           // 288 floats per channel plane
#define BUF (5*YB)             // 1440 floats per ych buffer

// 1-D separable Gaussian (sigma=1.5, window=5), normalized; literals -> FFMA-imm.
#define G0 0.12007838f
#define G1 0.23388076f
#define G2 0.29208171f

#define C1f 1.0e-4f            // 0.01^2
#define C2f 9.0e-4f            // 0.03^2

__device__ float g_partials[NBLOCKS];

// no-op: aligns ncu -s 5 onto ssim_main (launch pattern [nop,main,nop,reduce])
__global__ void knop() {}

__global__ void __launch_bounds__(NTHREADS, 2)
ssim_main(const float* __restrict__ X, const float* __restrict__ Y)
{
    __shared__ float ych[2 * BUF];     // double-buffered 5-channel y-convolved planes

    const int tid = threadIdx.x;
    const int nc  = blockIdx.z >> 1;                 // 0..7 (n*4 + c)
    const int zb  = (blockIdx.z & 1) * ZCHUNK;       // 0 or 64
    const int y0  = blockIdx.y * TY;
    const int x0  = blockIdx.x * TX;
    const float* Xb = X + (size_t)nc * (128 * 128 * 128);
    const float* Yb = Y + (size_t)nc * (128 * 128 * 128);

    // ---------- loop-invariant task geometry: one (yy,w) task per thread ----
    const int yy = tid / HXP;          // 0..7
    const int w  = tid - yy * HXP;     // 0..35
    const int gh = y0 + yy - 2;
    const int gw = x0 + w - 2;
    unsigned rm = 0;
    #pragma unroll
    for (int t = 0; t < 5; t++)
        if ((unsigned)(gh + t) < 128u && (unsigned)gw < 128u) rm |= 1u << t;
    const float* px = Xb + ((zb - 2) * 16384 + gh * 128 + gw);
    const float* py = Yb + ((zb - 2) * 16384 + gh * 128 + gw);

    // phase-2 output column (warps 0-7 only)
    const int ox = tid & 31;
    const int oy = tid >> 5;
    const int xb = oy * HXP + ox;
    const bool doOut = (tid < 256);

    // z-conv ring accumulators: 5 channels x 5 in-flight output planes
    float a0[5], a1[5], a2[5], a3[5], a4[5];
    #pragma unroll
    for (int i = 0; i < 5; i++) { a0[i] = a1[i] = a2[i] = a3[i] = a4[i] = 0.f; }

    float lsum = 0.f;
    const float GW[5] = {G0, G1, G2, G1, G0};

    // ---------- prefetch plane it=0 (zp = zb-2) ----------
    float pvx[5], pvy[5];
    {
        const bool zok = (unsigned)(zb - 2) < 128u;
        #pragma unroll
        for (int t = 0; t < 5; t++) {
            const bool m = zok && ((rm >> t) & 1);
            pvx[t] = m ? px[t * 128] : 0.f;
            pvy[t] = m ? py[t * 128] : 0.f;
        }
    }

    int pb = 0;
    int zp = zb - 2;

    for (int grp = 0; grp < 14; ++grp) {
        #pragma unroll
        for (int s = 0; s < 5; ++s) {
            const int it = grp * 5 + s;

            // ---- phase 1: channel formation + y-conv from prefetched regs ----
            {
                float s0 = 0.f, s1 = 0.f, s2 = 0.f, s3 = 0.f, s4 = 0.f;
                #pragma unroll
                for (int t = 0; t < 5; t++) {
                    float a = fmaf(pvx[t], 0.5f, 0.5f);
                    float b = fmaf(pvy[t], 0.5f, 0.5f);
                    // masked-out taps carry pv=0 -> a=b=0.5; kill via mask-scaled weight
                    float g = ((rm >> t) & 1) ? GW[t] : 0.f;
                    float ga = g * a, gb = g * b;
                    s0 += ga;
                    s1 += gb;
                    s2 = fmaf(ga, a, s2);
                    s3 = fmaf(gb, b, s3);
                    s4 = fmaf(ga, b, s4);
                }
                // zp out of range => whole plane must be zero
                if ((unsigned)zp >= 128u) { s0 = s1 = s2 = s3 = s4 = 0.f; }
                float* wr = ych + pb + tid;
                wr[0]      = s0;
                wr[YB]     = s1;
                wr[2 * YB] = s2;
                wr[3 * YB] = s3;
                wr[4 * YB] = s4;
            }
            __syncthreads();    // single barrier per plane

            // ---- prefetch next plane (overlaps phase 2 compute) ----
            px += 16384; py += 16384; zp++;
            {
                const bool zok = (unsigned)zp < 128u;
                #pragma unroll
                for (int t = 0; t < 5; t++) {
                    const bool m = zok && ((rm >> t) & 1);
                    pvx[t] = m ? px[t * 128] : 0.f;
                    pvy[t] = m ? py[t * 128] : 0.f;
                }
            }

            if (doOut) {
                // ---- phase 2: x-conv ----
                const float* rd = ych + pb + xb;
                #define XC(c) (G2 * rd[(c)*YB + 2] \
                             + G1 * (rd[(c)*YB + 1] + rd[(c)*YB + 3]) \
                             + G0 * (rd[(c)*YB] + rd[(c)*YB + 4]))
                float v0 = XC(0), v1 = XC(1), v2 = XC(2), v3 = XC(3), v4 = XC(4);
                #undef XC

                // ---- z accumulation (slot index static after unroll) ----
                #pragma unroll
                for (int k = 0; k < 5; ++k) {
                    const int sl = (s + k) % 5;
                    float g = GW[k];
                    a0[sl] = fmaf(g, v0, a0[sl]);
                    a1[sl] = fmaf(g, v1, a1[sl]);
                    a2[sl] = fmaf(g, v2, a2[sl]);
                    a3[sl] = fmaf(g, v3, a3[sl]);
                    a4[sl] = fmaf(g, v4, a4[sl]);
                }

                // ---- slot s complete -> SSIM for output plane zb + it - 4 ----
                if ((unsigned)(it - 4) < 64u) {
                    float mu1 = a0[s], mu2 = a1[s];
                    float mu1s = mu1 * mu1, mu2s = mu2 * mu2, mu12 = mu1 * mu2;
                    float sg1  = a2[s] - mu1s;
                    float sg2  = a3[s] - mu2s;
                    float sg12 = a4[s] - mu12;
                    float num = (2.f * mu12 + C1f) * (2.f * sg12 + C2f);
                    float den = (mu1s + mu2s + C1f) * (sg1 + sg2 + C2f);
                    lsum += __fdividef(num, den);
                }
                a0[s] = 0.f; a1[s] = 0.f; a2[s] = 0.f; a3[s] = 0.f; a4[s] = 0.f;
            }

            pb ^= BUF;
        }
    }

    // ---- block reduction (9 warps) ----
    #pragma unroll
    for (int o = 16; o; o >>= 1)
        lsum += __shfl_xor_sync(0xffffffffu, lsum, o);
    __syncthreads();
    if ((tid & 31) == 0) ych[tid >> 5] = lsum;
    __syncthreads();
    if (tid == 0) {
        float t = 0.f;
        #pragma unroll
        for (int i = 0; i < 9; i++) t += ych[i];
        g_partials[(blockIdx.z * 16 + blockIdx.y) * 4 + blockIdx.x] = t;
    }
}

__global__ void ssim_reduce(float* __restrict__ out)
{
    __shared__ double sd[256];
    double s = 0.0;
    for (int i = threadIdx.x; i < NBLOCKS; i += 256)
        s += (double)g_partials[i];
    sd[threadIdx.x] = s;
    __syncthreads();
    #pragma unroll
    for (int st = 128; st; st >>= 1) {
        if (threadIdx.x < st) sd[threadIdx.x] += sd[threadIdx.x + st];
        __syncthreads();
    }
    if (threadIdx.x == 0)
        out[0] = (float)(sd[0] * (1.0 / 16777216.0));
}

extern "C" void kernel_launch(void* const* d_in, const int* in_sizes, int n_in,
                              void* d_out, int out_size)
{
    const float* X = (const float*)d_in[0];
    const float* Y = (const float*)d_in[1];
    // d_in[2] is the Gaussian kernel; weights are baked in as literals.

    dim3 grid(4, 16, 16);    // x-tiles, y-tiles, nc*2 z-chunks
    knop<<<1, 32>>>();                          // launch-index padding for ncu -s 5
    ssim_main<<<grid, NTHREADS>>>(X, Y);
    knop<<<1, 32>>>();
    ssim_reduce<<<1, 256>>>((float*)d_out);
}